// round 16
// baseline (speedup 1.0000x reference)
#include <cuda_runtime.h>
#include <cuda_fp16.h>
#include <cstdint>
#include <math.h>

// Problem constants
#define CB 4
#define CT 1024
#define CC 1024
#define CH 16
#define CD 64
#define CM (CB*CT)   // 4096 rows

// ---------------- device scratch (no allocation allowed) ----------------
__device__ __half g_qh[CB*CH*CT*CD];   // [b,h,t,d] q fp16, rope applied, scaled 0.125*log2e
__device__ __half g_kh[CB*CH*CT*CD];   // k fp16, rope applied
__device__ __half g_vh[CB*CH*CT*CD];   // v fp16

__device__ __half g_xh[CM*CC];         // x fp16
__device__ __half g_wh[4*CC*CC];       // Wq,Wk,Wv,Wo fp16
__device__ __half g_ao[CM*CC];         // attention out fp16 [b,t, h*64+d]
__device__ float g_cs[CT*32];
__device__ float g_sn[CT*32];

// ---------------- helpers ----------------
static __device__ __forceinline__ uint32_t smem_u32(const void* p) {
    uint32_t a;
    asm("{ .reg .u64 t; cvta.to.shared.u64 t, %1; cvt.u32.u64 %0, t; }" : "=r"(a) : "l"(p));
    return a;
}
static __device__ __forceinline__ void cpasync16(uint32_t s, const void* g) {
    asm volatile("cp.async.cg.shared.global [%0], [%1], 16;" :: "r"(s), "l"(g));
}
#define CP_COMMIT() asm volatile("cp.async.commit_group;" ::: "memory")
#define CP_WAIT1()  asm volatile("cp.async.wait_group 1;" ::: "memory")
#define CP_WAIT0()  asm volatile("cp.async.wait_group 0;" ::: "memory")

#define LDSM_X4(r0, r1, r2, r3, addr) \
    asm volatile("ldmatrix.sync.aligned.m8n8.x4.shared.b16 {%0,%1,%2,%3}, [%4];" \
        : "=r"(r0), "=r"(r1), "=r"(r2), "=r"(r3) : "r"(addr))

#define LDSM_X4T(r0, r1, r2, r3, addr) \
    asm volatile("ldmatrix.sync.aligned.m8n8.x4.trans.shared.b16 {%0,%1,%2,%3}, [%4];" \
        : "=r"(r0), "=r"(r1), "=r"(r2), "=r"(r3) : "r"(addr))

#define MMA_F16(c, a, b0_, b1_) \
    asm volatile("mma.sync.aligned.m16n8k16.row.col.f32.f16.f16.f32 " \
        "{%0,%1,%2,%3}, {%4,%5,%6,%7}, {%8,%9}, {%0,%1,%2,%3};" \
        : "+f"((c)[0]), "+f"((c)[1]), "+f"((c)[2]), "+f"((c)[3]) \
        : "r"((a)[0]), "r"((a)[1]), "r"((a)[2]), "r"((a)[3]), "r"(b0_), "r"(b1_))

static __device__ __forceinline__ float ex2f(float x) {
    float r; asm("ex2.approx.ftz.f32 %0, %1;" : "=f"(r) : "f"(x)); return r;
}
static __device__ __forceinline__ uint32_t pack_h2(float x0, float x1) {
    __half2 h = __floats2half2_rn(x0, x1);
    return *reinterpret_cast<uint32_t*>(&h);
}

// swizzled smem address: 128B rows, 16B chunk j of row r lives at slot j^(r&7)
static __device__ __forceinline__ uint32_t swz(int row, int chunk) {
    return (uint32_t)(row * 128 + ((chunk ^ (row & 7)) << 4));
}

// ==================== fused pre-pass kernel (MLP=4) ====================
// grid.x: [0,1024) x fp16 (4 float4/thr) | [1024,2048) W fp16 (256 blk/z, 4 float4/thr)
//         | [2048,2176) rope tables
__global__ void __launch_bounds__(256) prepass_kernel(
    const float* __restrict__ x,
    const float* __restrict__ Wq, const float* __restrict__ Wk,
    const float* __restrict__ Wv, const float* __restrict__ Wo)
{
    int bid = blockIdx.x;
    int tid = threadIdx.x;
    if (bid < 1024) {
        int base = bid * 1024 + tid;
        float4 v[4];
        #pragma unroll
        for (int u = 0; u < 4; u++) v[u] = ((const float4*)x)[base + 256*u];
        #pragma unroll
        for (int u = 0; u < 4; u++)
            ((uint2*)g_xh)[base + 256*u] =
                make_uint2(pack_h2(v[u].x, v[u].y), pack_h2(v[u].z, v[u].w));
    } else if (bid < 2048) {
        int z = (bid - 1024) >> 8;
        int lb = (bid - 1024) & 255;
        const float* W = (z == 0) ? Wq : ((z == 1) ? Wk : ((z == 2) ? Wv : Wo));
        __half* dst = g_wh + (size_t)z * (CC*CC);
        int base = lb * 1024 + tid;
        float4 v[4];
        #pragma unroll
        for (int u = 0; u < 4; u++) v[u] = ((const float4*)W)[base + 256*u];
        #pragma unroll
        for (int u = 0; u < 4; u++)
            ((uint2*)dst)[base + 256*u] =
                make_uint2(pack_h2(v[u].x, v[u].y), pack_h2(v[u].z, v[u].w));
    } else {
        int idx = (bid - 2048) * 256 + tid;   // [0, 32768)
        int t = idx >> 5, p = idx & 31;
        float invf = (float)exp(-0.28782313662425575 * (double)p);  // 10000^(-p/32)
        float fr = (float)t * invf;
        float s, c;
        sincosf(fr, &s, &c);
        g_cs[idx] = c;
        g_sn[idx] = s;
    }
}

// ==================== qkv GEMM core (fp16, 128 thr, CTA tile 64x128, 3-stage, SW128) ====================
// C[64,128] at (m0,n0): 4 warps of 64x32 (wm=0). smem/stage: A 8KB | B 16KB = 24KB. 3 stages = 72KB.
#define QTEN_A 8192
#define QSTG_B 24576
#define QKV_SMEM (3*QSTG_B)   // 73728 -> 3 CTAs/SM

struct GemmOut { float acc[4][4][4]; };   // [mi 16][nj 8][frag]

static __device__ __forceinline__ void qkv_gemm_core(
    const __half* __restrict__ A, const __half* __restrict__ B,
    int m0, int n0, char* smraw, GemmOut& out)
{
    const int tid = threadIdx.x;     // 128 threads
    const int lane = tid & 31;
    const int wid = tid >> 5;        // 4 warps, 1x4: warp tile 64x32, wm = 0
    const int wn = wid * 32;

    uint32_t sbase = smem_u32(smraw);

    #pragma unroll
    for (int i = 0; i < 4; i++)
        #pragma unroll
        for (int j = 0; j < 4; j++)
            #pragma unroll
            for (int q = 0; q < 4; q++) out.acc[i][j][q] = 0.f;

    // A: 64 rows x 8 chunks = 512 chunks, 4/thread. B: 128 rows x 8 = 1024 chunks, 8/thread.
    uint32_t smeA[4];
    long gmeA[4];
    #pragma unroll
    for (int i = 0; i < 4; i++) {
        int c = tid + 128 * i;
        int r = c >> 3, j = c & 7;
        smeA[i] = swz(r, j);
        gmeA[i] = (long)r * 2048 + j * 16;
    }
    uint32_t smeB[8];
    long gmeB[8];
    #pragma unroll
    for (int i = 0; i < 8; i++) {
        int c = tid + 128 * i;
        int r = c >> 3, j = c & 7;
        smeB[i] = swz(r, j);
        gmeB[i] = (long)r * 2048 + j * 16;
    }

    const char* gA = (const char*)(A + (size_t)m0 * 1024);
    const char* gB = (const char*)(B + (size_t)n0 * 1024);

    // LDSM row/swizzle precompute
    const int arow = lane & 15;            // + i*16, rows 0..63
    const int as7  = arow & 7;
    const int ac0  = lane >> 4;
    const int brow = wn + (lane & 7) + ((lane >> 4) & 1) * 8;
    const int bs7  = brow & 7;
    const int bc0  = (lane >> 3) & 1;
    const uint32_t arb = (uint32_t)(arow * 128);
    const uint32_t brb = (uint32_t)(brow * 128);

    // prologue: chunks 0,1 -> stages 0,1
    #pragma unroll
    for (int p = 0; p < 2; p++) {
        uint32_t st = sbase + p * QSTG_B;
        long kb = (long)p * 128;
        #pragma unroll
        for (int i = 0; i < 4; i++) cpasync16(st + smeA[i], gA + kb + gmeA[i]);
        #pragma unroll
        for (int i = 0; i < 8; i++) cpasync16(st + QTEN_A + smeB[i], gB + kb + gmeB[i]);
        CP_COMMIT();
    }

    #pragma unroll 1
    for (int cc = 0; cc < 16; cc++) {
        if (cc < 15) { CP_WAIT1(); } else { CP_WAIT0(); }
        __syncthreads();
        if (cc + 2 < 16) {
            uint32_t st = sbase + ((cc + 2) % 3) * QSTG_B;
            long kb = (long)(cc + 2) * 128;
            #pragma unroll
            for (int i = 0; i < 4; i++) cpasync16(st + smeA[i], gA + kb + gmeA[i]);
            #pragma unroll
            for (int i = 0; i < 8; i++) cpasync16(st + QTEN_A + smeB[i], gB + kb + gmeB[i]);
            CP_COMMIT();
        }

        uint32_t st = sbase + (cc % 3) * QSTG_B;

        #pragma unroll
        for (int ks = 0; ks < 4; ks++) {
            uint32_t ah[4][4], bh[2][4];
            #pragma unroll
            for (int i = 0; i < 4; i++) {
                uint32_t a_ad = st + arb + (uint32_t)(i * (16*128))
                              + (uint32_t)((((ks*2 + ac0) ^ as7)) << 4);
                LDSM_X4(ah[i][0], ah[i][1], ah[i][2], ah[i][3], a_ad);
            }
            #pragma unroll
            for (int j = 0; j < 2; j++) {
                uint32_t b_ad = st + QTEN_A + brb + (uint32_t)(j * (16*128))
                              + (uint32_t)((((ks*2 + bc0) ^ bs7)) << 4);
                LDSM_X4(bh[j][0], bh[j][1], bh[j][2], bh[j][3], b_ad);
            }
            #pragma unroll
            for (int i = 0; i < 4; i++) {
                #pragma unroll
                for (int j = 0; j < 4; j++) {
                    int jj = j >> 1, sel = (j & 1) * 2;
                    MMA_F16(out.acc[i][j], ah[i], bh[jj][sel], bh[jj][sel+1]);
                }
            }
        }
    }
}

// ==================== oproj GEMM core (fp16, 256 thr, 128x128, 3-stage, SW128) ====================
#define TEN_B 16384
#define STG_B (2*TEN_B)       // 32768
#define GEMM_SMEM (3*STG_B)   // 98304 -> 2 CTAs/SM

static __device__ __forceinline__ void gemm_hmma(
    const __half* __restrict__ A, const __half* __restrict__ B,
    int m0, int n0, char* smraw, GemmOut& out)
{
    const int tid = threadIdx.x;     // 256 threads
    const int lane = tid & 31;
    const int wid = tid >> 5;        // 8 warps, 2x4: warp tile 64x32
    const int wm = (wid >> 2) * 64;
    const int wn = (wid & 3) * 32;

    uint32_t sbase = smem_u32(smraw);

    #pragma unroll
    for (int i = 0; i < 4; i++)
        #pragma unroll
        for (int j = 0; j < 4; j++)
            #pragma unroll
            for (int q = 0; q < 4; q++) out.acc[i][j][q] = 0.f;

    uint32_t sme[4];
    long gme[4];
    #pragma unroll
    for (int i = 0; i < 4; i++) {
        int c = tid + 256 * i;
        int r = c >> 3, j = c & 7;
        sme[i] = swz(r, j);
        gme[i] = (long)r * 2048 + j * 16;
    }

    const char* gA = (const char*)(A + (size_t)m0 * 1024);
    const char* gB = (const char*)(B + (size_t)n0 * 1024);

    const int arow = wm + (lane & 15);
    const int as7  = arow & 7;
    const int ac0  = lane >> 4;
    const int brow = wn + (lane & 7) + ((lane >> 4) & 1) * 8;
    const int bs7  = brow & 7;
    const int bc0  = (lane >> 3) & 1;
    const uint32_t arb = (uint32_t)(arow * 128);
    const uint32_t brb = (uint32_t)(brow * 128);

    #pragma unroll
    for (int p = 0; p < 2; p++) {
        uint32_t st = sbase + p * STG_B;
        long kb = (long)p * 128;
        #pragma unroll
        for (int i = 0; i < 4; i++) {
            cpasync16(st + sme[i],         gA + kb + gme[i]);
            cpasync16(st + TEN_B + sme[i], gB + kb + gme[i]);
        }
        CP_COMMIT();
    }

    #pragma unroll 1
    for (int cc = 0; cc < 16; cc++) {
        if (cc < 15) { CP_WAIT1(); } else { CP_WAIT0(); }
        __syncthreads();
        if (cc + 2 < 16) {
            uint32_t st = sbase + ((cc + 2) % 3) * STG_B;
            long kb = (long)(cc + 2) * 128;
            #pragma unroll
            for (int i = 0; i < 4; i++) {
                cpasync16(st + sme[i],         gA + kb + gme[i]);
                cpasync16(st + TEN_B + sme[i], gB + kb + gme[i]);
            }
            CP_COMMIT();
        }

        uint32_t st = sbase + (cc % 3) * STG_B;

        #pragma unroll
        for (int ks = 0; ks < 4; ks++) {
            uint32_t ah[4][4], bh[2][4];
            #pragma unroll
            for (int i = 0; i < 4; i++) {
                uint32_t a_ad = st + arb + (uint32_t)(i * (16*128))
                              + (uint32_t)((((ks*2 + ac0) ^ as7)) << 4);
                LDSM_X4(ah[i][0], ah[i][1], ah[i][2], ah[i][3], a_ad);
            }
            #pragma unroll
            for (int j = 0; j < 2; j++) {
                uint32_t b_ad = st + TEN_B + brb + (uint32_t)(j * (16*128))
                              + (uint32_t)((((ks*2 + bc0) ^ bs7)) << 4);
                LDSM_X4(bh[j][0], bh[j][1], bh[j][2], bh[j][3], b_ad);
            }
            #pragma unroll
            for (int i = 0; i < 4; i++) {
                #pragma unroll
                for (int j = 0; j < 4; j++) {
                    int jj = j >> 1, sel = (j & 1) * 2;
                    MMA_F16(out.acc[i][j], ah[i], bh[jj][sel], bh[jj][sel+1]);
                }
            }
        }
    }
}

// ==================== QKV projection + RoPE + fp16 epilogue (64-row tiles) ====================
#define QSCL 0.18033688011112042f   // 0.125 * log2(e)

__global__ void __launch_bounds__(128, 3) qkv_hmma() {
    extern __shared__ char smraw[];
    int z = blockIdx.z;
    int m0 = blockIdx.y * 64, n0 = blockIdx.x * 128;

    GemmOut o;
    qkv_gemm_core(g_xh, g_wh + (size_t)z * (CC*CC), m0, n0, smraw, o);

    const int tid = threadIdx.x;
    const int wid = tid >> 5;
    const int lane = tid & 31;
    const int wn = wid * 32;

    bool rope = (z < 2);

    int nbase = n0 + wn + (lane & 3) * 2;  // even
    #pragma unroll
    for (int i = 0; i < 4; i++) {
        #pragma unroll
        for (int rr = 0; rr < 2; rr++) {
            int m = m0 + i * 16 + (lane >> 2) + rr * 8;
            int b = m >> 10, t = m & 1023;
            #pragma unroll
            for (int j = 0; j < 4; j++) {
                int n = nbase + j * 8;
                int h = n >> 6, dl = n & 63;
                float x0 = o.acc[i][j][rr*2 + 0];
                float x1 = o.acc[i][j][rr*2 + 1];
                if (rope) {
                    int p = dl >> 1;
                    float c = g_cs[t*32 + p], s = g_sn[t*32 + p];
                    float y0 = x0 * c - x1 * s;
                    float y1 = x0 * s + x1 * c;
                    x0 = y0; x1 = y1;
                }
                size_t off = ((size_t)(b * CH + h) * CT + t) * CD + dl;
                if (z == 0) {
                    *(uint32_t*)(g_qh + off) = pack_h2(x0 * QSCL, x1 * QSCL);
                } else if (z == 1) {
                    *(uint32_t*)(g_kh + off) = pack_h2(x0, x1);
                } else {
                    *(uint32_t*)(g_vh + off) = pack_h2(x0, x1);
                }
            }
        }
    }
}

// ==================== output projection ====================
__global__ void __launch_bounds__(256, 2) oproj_hmma(float* __restrict__ outp) {
    extern __shared__ char smraw[];
    int m0 = blockIdx.y * 128, n0 = blockIdx.x * 128;

    GemmOut o;
    gemm_hmma(g_ao, g_wh + (size_t)3 * (CC*CC), m0, n0, smraw, o);

    const int tid = threadIdx.x;
    const int wid = tid >> 5;
    const int lane = tid & 31;
    const int wm = (wid >> 2) * 64;
    const int wn = (wid & 3) * 32;

    int nbase = n0 + wn + (lane & 3) * 2;
    #pragma unroll
    for (int i = 0; i < 4; i++) {
        #pragma unroll
        for (int rr = 0; rr < 2; rr++) {
            int m = m0 + wm + i * 16 + (lane >> 2) + rr * 8;
            #pragma unroll
            for (int j = 0; j < 4; j++) {
                int n = nbase + j * 8;
                *(float2*)(outp + (size_t)m * CC + n) =
                    make_float2(o.acc[i][j][rr*2 + 0], o.acc[i][j][rr*2 + 1]);
            }
        }
    }
}

// ==================== HMMA flash attention (causal, no-max softmax, fp16, SW128) ====================
#define ATILE 16384
#define ATTN_SMEM (5*ATILE)   // 81920

__global__ void __launch_bounds__(256) attn_hmma() {
    extern __shared__ char smraw[];
    uint32_t sb = smem_u32(smraw);
    uint32_t sQh = sb;
    uint32_t sK0 = sb + ATILE,    sK1 = sb + 2*ATILE;
    uint32_t sV0 = sb + 3*ATILE,  sV1 = sb + 4*ATILE;

    const int tid = threadIdx.x;
    const int wid = tid >> 5;
    const int lane = tid & 31;
    const int bh = blockIdx.y;
    const int b = bh >> 4, h = bh & 15;

    const char* qhb = (const char*)(g_qh + (size_t)bh * (CT*CD));
    const char* khb = (const char*)(g_kh + (size_t)bh * (CT*CD));
    const char* vhb = (const char*)(g_vh + (size_t)bh * (CT*CD));

    int rowc[4], colc[4];
    uint32_t smc[4];
    #pragma unroll
    for (int i = 0; i < 4; i++) {
        int c = tid + 256 * i;
        int r = c >> 3, j = c & 7;
        rowc[i] = r;
        colc[i] = j * 16;
        smc[i] = swz(r, j);
    }

    const int qrow = wid*16 + (lane & 15);
    const int qs7  = qrow & 7;
    const int qc0  = lane >> 4;
    const uint32_t qrb = (uint32_t)(qrow * 128);

    const int klr = (lane & 7) + ((lane >> 4) & 1) * 8;
    const int kc0 = (lane >> 3) & 1;

    const int vlr = (lane & 7) + ((lane >> 3) & 1) * 8;
    const int vc0 = (lane >> 4) & 1;

    #pragma unroll 1
    for (int pass = 0; pass < 2; pass++) {
        int qt = (pass == 0) ? blockIdx.x : 7 - blockIdx.x;

        #pragma unroll
        for (int i = 0; i < 4; i++) {
            long g = (long)(qt*128 + rowc[i]) * 128 + colc[i];
            cpasync16(sQh + smc[i], qhb + g);
        }
        CP_COMMIT();
        #pragma unroll
        for (int i = 0; i < 4; i++) {
            long g = (long)(rowc[i]) * 128 + colc[i];   // kt = 0
            cpasync16(sK0 + smc[i], khb + g);
            cpasync16(sV0 + smc[i], vhb + g);
        }
        CP_COMMIT();

        CP_WAIT1();
        __syncthreads();

        uint32_t qf[4][4];
        #pragma unroll
        for (int ks = 0; ks < 4; ks++) {
            uint32_t q_ad = sQh + qrb + (uint32_t)((((ks*2 + qc0) ^ qs7)) << 4);
            LDSM_X4(qf[ks][0], qf[ks][1], qf[ks][2], qf[ks][3], q_ad);
        }

        float o[8][4];
        #pragma unroll
        for (int j = 0; j < 8; j++)
            #pragma unroll
            for (int q = 0; q < 4; q++) o[j][q] = 0.f;
        float lsum0 = 0.f, lsum1 = 0.f;

        #pragma unroll 1
        for (int kt = 0; kt <= qt; kt++) {
            CP_WAIT0();
            __syncthreads();
            if (kt < qt) {
                uint32_t sKn = ((kt+1) & 1) ? sK1 : sK0;
                uint32_t sVn = ((kt+1) & 1) ? sV1 : sV0;
                #pragma unroll
                for (int i = 0; i < 4; i++) {
                    long g = (long)((kt+1)*128 + rowc[i]) * 128 + colc[i];
                    cpasync16(sKn + smc[i], khb + g);
                    cpasync16(sVn + smc[i], vhb + g);
                }
                CP_COMMIT();
            }
            uint32_t sKh = (kt & 1) ? sK1 : sK0;
            uint32_t sVh = (kt & 1) ? sV1 : sV0;

            float s[16][4];
            #pragma unroll
            for (int f = 0; f < 16; f++)
                #pragma unroll
                for (int q = 0; q < 4; q++) s[f][q] = 0.f;

            #pragma unroll
            for (int ks = 0; ks < 4; ks++) {
                #pragma unroll
                for (int g = 0; g < 8; g++) {
                    int krow = g*16 + klr;
                    uint32_t k_ad = sKh + (uint32_t)(krow * 128)
                                  + (uint32_t)((((ks*2 + kc0) ^ (krow & 7))) << 4);
                    uint32_t k4[4];
                    LDSM_X4(k4[0], k4[1], k4[2], k4[3], k_ad);
                    MMA_F16(s[2*g],   qf[ks], k4[0], k4[1]);
                    MMA_F16(s[2*g+1], qf[ks], k4[2], k4[3]);
                }
            }

            bool diag = (kt == qt);
            int lrow = wid*16 + (lane >> 2);
            uint32_t ph_[16][2];
            #pragma unroll
            for (int f = 0; f < 16; f++) {
                int lcol = 8*f + 2*(lane & 3);
                float p0 = ex2f(s[f][0]);
                float p1 = ex2f(s[f][1]);
                float p2 = ex2f(s[f][2]);
                float p3 = ex2f(s[f][3]);
                if (diag) {
                    if (lcol     > lrow)     p0 = 0.f;
                    if (lcol + 1 > lrow)     p1 = 0.f;
                    if (lcol     > lrow + 8) p2 = 0.f;
                    if (lcol + 1 > lrow + 8) p3 = 0.f;
                }
                lsum0 += p0 + p1;
                lsum1 += p2 + p3;
                ph_[f][0] = pack_h2(p0, p1);
                ph_[f][1] = pack_h2(p2, p3);
            }

            #pragma unroll
            for (int ks = 0; ks < 8; ks++) {
                uint32_t ah[4] = {ph_[2*ks][0], ph_[2*ks][1], ph_[2*ks+1][0], ph_[2*ks+1][1]};
                int vrow = ks*16 + vlr;
                uint32_t vrb = sVh + (uint32_t)(vrow * 128);
                int v7 = vrow & 7;
                #pragma unroll
                for (int g2 = 0; g2 < 4; g2++) {
                    uint32_t v_ad = vrb + (uint32_t)((((g2*2 + vc0) ^ v7)) << 4);
                    uint32_t v4[4];
                    LDSM_X4T(v4[0], v4[1], v4[2], v4[3], v_ad);
                    MMA_F16(o[2*g2],   ah, v4[0], v4[1]);
                    MMA_F16(o[2*g2+1], ah, v4[2], v4[3]);
                }
            }
        }

        lsum0 += __shfl_xor_sync(0xffffffffu, lsum0, 1);
        lsum0 += __shfl_xor_sync(0xffffffffu, lsum0, 2);
        lsum1 += __shfl_xor_sync(0xffffffffu, lsum1, 1);
        lsum1 += __shfl_xor_sync(0xffffffffu, lsum1, 2);
        float inv0 = 1.0f / lsum0;
        float inv1 = 1.0f / lsum1;

        int t0g = qt*128 + wid*16 + (lane >> 2);
        #pragma unroll
        for (int j = 0; j < 8; j++) {
            int d = 8*j + 2*(lane & 3);
            size_t off0 = ((size_t)(b*CT) + t0g) * CC + h*CD + d;
            size_t off1 = off0 + (size_t)8 * CC;
            *(uint32_t*)(g_ao + off0) = pack_h2(o[j][0]*inv0, o[j][1]*inv0);
            *(uint32_t*)(g_ao + off1) = pack_h2(o[j][2]*inv1, o[j][3]*inv1);
        }
        __syncthreads();
    }
}

// ==================== launch ====================
extern "C" void kernel_launch(void* const* d_in, const int* in_sizes, int n_in,
                              void* d_out, int out_size)
{
    const float* x  = (const float*)d_in[0];
    const float* Wq = (const float*)d_in[1];
    const float* Wk = (const float*)d_in[2];
    const float* Wv = (const float*)d_in[3];
    const float* Wo = (const float*)d_in[4];
    float* outp = (float*)d_out;

    cudaFuncSetAttribute(qkv_hmma, cudaFuncAttributeMaxDynamicSharedMemorySize, QKV_SMEM);
    cudaFuncSetAttribute(oproj_hmma, cudaFuncAttributeMaxDynamicSharedMemorySize, GEMM_SMEM);
    cudaFuncSetAttribute(attn_hmma, cudaFuncAttributeMaxDynamicSharedMemorySize, ATTN_SMEM);

    prepass_kernel<<<2176, 256>>>(x, Wq, Wk, Wv, Wo);

    dim3 gqkv(CC/128, CM/64, 3);     // (8, 64, 3) = 1536 CTAs
    qkv_hmma<<<gqkv, 128, QKV_SMEM>>>();

    dim3 gattn(4, CB*CH);            // qtile pairs (qt, 7-qt) x 64 bh
    attn_hmma<<<gattn, 256, ATTN_SMEM>>>();

    dim3 gout(CC/128, CM/128);       // (8, 32)
    oproj_hmma<<<gout, 256, GEMM_SMEM>>>(outp);
}

// round 17
// speedup vs baseline: 1.0124x; 1.0124x over previous
#include <cuda_runtime.h>
#include <cuda_fp16.h>
#include <cstdint>
#include <math.h>

// Problem constants
#define CB 4
#define CT 1024
#define CC 1024
#define CH 16
#define CD 64
#define CM (CB*CT)   // 4096 rows

// ---------------- device scratch (no allocation allowed) ----------------
__device__ __half g_qh[CB*CH*CT*CD];   // [b,h,t,d] q fp16, rope applied, scaled 0.125*log2e
__device__ __half g_kh[CB*CH*CT*CD];   // k fp16, rope applied
__device__ __half g_vh[CB*CH*CT*CD];   // v fp16

__device__ __half g_xh[CM*CC];         // x fp16
__device__ __half g_wh[4*CC*CC];       // Wq,Wk,Wv,Wo fp16
__device__ __half g_ao[CM*CC];         // attention out fp16 [b,t, h*64+d]
__device__ float g_cs[CT*32];
__device__ float g_sn[CT*32];

// ---------------- helpers ----------------
static __device__ __forceinline__ uint32_t smem_u32(const void* p) {
    uint32_t a;
    asm("{ .reg .u64 t; cvta.to.shared.u64 t, %1; cvt.u32.u64 %0, t; }" : "=r"(a) : "l"(p));
    return a;
}
static __device__ __forceinline__ void cpasync16(uint32_t s, const void* g) {
    asm volatile("cp.async.cg.shared.global [%0], [%1], 16;" :: "r"(s), "l"(g));
}
#define CP_COMMIT() asm volatile("cp.async.commit_group;" ::: "memory")
#define CP_WAIT1()  asm volatile("cp.async.wait_group 1;" ::: "memory")
#define CP_WAIT0()  asm volatile("cp.async.wait_group 0;" ::: "memory")

#define LDSM_X4(r0, r1, r2, r3, addr) \
    asm volatile("ldmatrix.sync.aligned.m8n8.x4.shared.b16 {%0,%1,%2,%3}, [%4];" \
        : "=r"(r0), "=r"(r1), "=r"(r2), "=r"(r3) : "r"(addr))

#define LDSM_X4T(r0, r1, r2, r3, addr) \
    asm volatile("ldmatrix.sync.aligned.m8n8.x4.trans.shared.b16 {%0,%1,%2,%3}, [%4];" \
        : "=r"(r0), "=r"(r1), "=r"(r2), "=r"(r3) : "r"(addr))

#define MMA_F16(c, a, b0_, b1_) \
    asm volatile("mma.sync.aligned.m16n8k16.row.col.f32.f16.f16.f32 " \
        "{%0,%1,%2,%3}, {%4,%5,%6,%7}, {%8,%9}, {%0,%1,%2,%3};" \
        : "+f"((c)[0]), "+f"((c)[1]), "+f"((c)[2]), "+f"((c)[3]) \
        : "r"((a)[0]), "r"((a)[1]), "r"((a)[2]), "r"((a)[3]), "r"(b0_), "r"(b1_))

static __device__ __forceinline__ float ex2f(float x) {
    float r; asm("ex2.approx.ftz.f32 %0, %1;" : "=f"(r) : "f"(x)); return r;
}
static __device__ __forceinline__ uint32_t pack_h2(float x0, float x1) {
    __half2 h = __floats2half2_rn(x0, x1);
    return *reinterpret_cast<uint32_t*>(&h);
}

// swizzled smem address: 128B rows, 16B chunk j of row r lives at slot j^(r&7)
static __device__ __forceinline__ uint32_t swz(int row, int chunk) {
    return (uint32_t)(row * 128 + ((chunk ^ (row & 7)) << 4));
}

// ==================== fused pre-pass kernel (MLP=8, streaming loads) ====================
// grid.x: [0,512) x fp16 (8 float4/thr) | [512,1024) W fp16 (128 blk/z, 8 float4/thr)
//         | [1024,1152) rope tables
__global__ void __launch_bounds__(256) prepass_kernel(
    const float* __restrict__ x,
    const float* __restrict__ Wq, const float* __restrict__ Wk,
    const float* __restrict__ Wv, const float* __restrict__ Wo)
{
    int bid = blockIdx.x;
    int tid = threadIdx.x;
    if (bid < 512) {
        int base = bid * 2048 + tid;
        float4 v[8];
        #pragma unroll
        for (int u = 0; u < 8; u++) v[u] = __ldcs(((const float4*)x) + base + 256*u);
        #pragma unroll
        for (int u = 0; u < 8; u++)
            ((uint2*)g_xh)[base + 256*u] =
                make_uint2(pack_h2(v[u].x, v[u].y), pack_h2(v[u].z, v[u].w));
    } else if (bid < 1024) {
        int z = (bid - 512) >> 7;
        int lb = (bid - 512) & 127;
        const float* W = (z == 0) ? Wq : ((z == 1) ? Wk : ((z == 2) ? Wv : Wo));
        __half* dst = g_wh + (size_t)z * (CC*CC);
        int base = lb * 2048 + tid;
        float4 v[8];
        #pragma unroll
        for (int u = 0; u < 8; u++) v[u] = __ldcs(((const float4*)W) + base + 256*u);
        #pragma unroll
        for (int u = 0; u < 8; u++)
            ((uint2*)dst)[base + 256*u] =
                make_uint2(pack_h2(v[u].x, v[u].y), pack_h2(v[u].z, v[u].w));
    } else {
        int idx = (bid - 1024) * 256 + tid;   // [0, 32768)
        int t = idx >> 5, p = idx & 31;
        float invf = (float)exp(-0.28782313662425575 * (double)p);  // 10000^(-p/32)
        float fr = (float)t * invf;
        float s, c;
        sincosf(fr, &s, &c);
        g_cs[idx] = c;
        g_sn[idx] = s;
    }
}

// ==================== HMMA GEMM core (fp16, 256 thr, warp 64x32, 3-stage, SW128) ====================
// C[128,128] at (m0,n0): C = sum_k A[m,k]*B[n,k], both fp16.
// 8 warps, 2x4 grid: warp tile 64x32. smem/stage: A|B 16KB each. 3 stages = 96KB.
#define TEN_B 16384
#define STG_B (2*TEN_B)       // 32768
#define GEMM_SMEM (3*STG_B)   // 98304 -> 2 CTAs/SM (16 warps)

struct GemmOut { float acc[4][4][4]; };   // [mi 16][nj 8][frag]

static __device__ __forceinline__ void gemm_hmma(
    const __half* __restrict__ A, const __half* __restrict__ B,
    int m0, int n0, char* smraw, GemmOut& out)
{
    const int tid = threadIdx.x;     // 256 threads
    const int lane = tid & 31;
    const int wid = tid >> 5;        // 8 warps, 2x4: warp tile 64x32
    const int wm = (wid >> 2) * 64;
    const int wn = (wid & 3) * 32;

    uint32_t sbase = smem_u32(smraw);

    #pragma unroll
    for (int i = 0; i < 4; i++)
        #pragma unroll
        for (int j = 0; j < 4; j++)
            #pragma unroll
            for (int q = 0; q < 4; q++) out.acc[i][j][q] = 0.f;

    // load mapping: per tensor 1024 16B-chunks (128 rows x 8), 4 per thread; swizzled STS
    uint32_t sme[4];
    long gme[4];
    #pragma unroll
    for (int i = 0; i < 4; i++) {
        int c = tid + 256 * i;
        int r = c >> 3, j = c & 7;
        sme[i] = swz(r, j);
        gme[i] = (long)r * 2048 + j * 16;
    }

    const char* gA = (const char*)(A + (size_t)m0 * 1024);
    const char* gB = (const char*)(B + (size_t)n0 * 1024);

    // LDSM row/swizzle precompute
    const int arow = wm + (lane & 15);
    const int as7  = arow & 7;
    const int ac0  = lane >> 4;             // 0/1 chunk within ks pair
    const int brow = wn + (lane & 7) + ((lane >> 4) & 1) * 8;
    const int bs7  = brow & 7;
    const int bc0  = (lane >> 3) & 1;
    const uint32_t arb = (uint32_t)(arow * 128);
    const uint32_t brb = (uint32_t)(brow * 128);

    // prologue: chunks 0,1 -> stages 0,1   (K-chunk = 64 halves = 128 bytes)
    #pragma unroll
    for (int p = 0; p < 2; p++) {
        uint32_t st = sbase + p * STG_B;
        long kb = (long)p * 128;
        #pragma unroll
        for (int i = 0; i < 4; i++) {
            cpasync16(st + sme[i],         gA + kb + gme[i]);
            cpasync16(st + TEN_B + sme[i], gB + kb + gme[i]);
        }
        CP_COMMIT();
    }

    #pragma unroll 1
    for (int cc = 0; cc < 16; cc++) {
        if (cc < 15) { CP_WAIT1(); } else { CP_WAIT0(); }
        __syncthreads();
        if (cc + 2 < 16) {
            uint32_t st = sbase + ((cc + 2) % 3) * STG_B;
            long kb = (long)(cc + 2) * 128;
            #pragma unroll
            for (int i = 0; i < 4; i++) {
                cpasync16(st + sme[i],         gA + kb + gme[i]);
                cpasync16(st + TEN_B + sme[i], gB + kb + gme[i]);
            }
            CP_COMMIT();
        }

        uint32_t st = sbase + (cc % 3) * STG_B;

        #pragma unroll
        for (int ks = 0; ks < 4; ks++) {
            uint32_t ah[4][4], bh[2][4];
            #pragma unroll
            for (int i = 0; i < 4; i++) {
                uint32_t a_ad = st + arb + (uint32_t)(i * (16*128))
                              + (uint32_t)((((ks*2 + ac0) ^ as7)) << 4);
                LDSM_X4(ah[i][0], ah[i][1], ah[i][2], ah[i][3], a_ad);
            }
            #pragma unroll
            for (int j = 0; j < 2; j++) {
                uint32_t b_ad = st + TEN_B + brb + (uint32_t)(j * (16*128))
                              + (uint32_t)((((ks*2 + bc0) ^ bs7)) << 4);
                LDSM_X4(bh[j][0], bh[j][1], bh[j][2], bh[j][3], b_ad);
            }
            #pragma unroll
            for (int i = 0; i < 4; i++) {
                #pragma unroll
                for (int j = 0; j < 4; j++) {
                    int jj = j >> 1, sel = (j & 1) * 2;
                    MMA_F16(out.acc[i][j], ah[i], bh[jj][sel], bh[jj][sel+1]);
                }
            }
        }
    }
}

// ==================== QKV projection + RoPE + fp16 epilogue ====================
#define QSCL 0.18033688011112042f   // 0.125 * log2(e)

__global__ void __launch_bounds__(256, 2) qkv_hmma() {
    extern __shared__ char smraw[];
    int z = blockIdx.z;
    int m0 = blockIdx.y * 128, n0 = blockIdx.x * 128;

    GemmOut o;
    gemm_hmma(g_xh, g_wh + (size_t)z * (CC*CC), m0, n0, smraw, o);

    const int tid = threadIdx.x;
    const int wid = tid >> 5;
    const int lane = tid & 31;
    const int wm = (wid >> 2) * 64;
    const int wn = (wid & 3) * 32;

    bool rope = (z < 2);

    int nbase = n0 + wn + (lane & 3) * 2;  // even
    #pragma unroll
    for (int i = 0; i < 4; i++) {
        #pragma unroll
        for (int rr = 0; rr < 2; rr++) {
            int m = m0 + wm + i * 16 + (lane >> 2) + rr * 8;
            int b = m >> 10, t = m & 1023;
            #pragma unroll
            for (int j = 0; j < 4; j++) {
                int n = nbase + j * 8;
                int h = n >> 6, dl = n & 63;
                float x0 = o.acc[i][j][rr*2 + 0];
                float x1 = o.acc[i][j][rr*2 + 1];
                if (rope) {
                    int p = dl >> 1;
                    float c = g_cs[t*32 + p], s = g_sn[t*32 + p];
                    float y0 = x0 * c - x1 * s;
                    float y1 = x0 * s + x1 * c;
                    x0 = y0; x1 = y1;
                }
                size_t off = ((size_t)(b * CH + h) * CT + t) * CD + dl;
                if (z == 0) {
                    *(uint32_t*)(g_qh + off) = pack_h2(x0 * QSCL, x1 * QSCL);
                } else if (z == 1) {
                    *(uint32_t*)(g_kh + off) = pack_h2(x0, x1);
                } else {
                    *(uint32_t*)(g_vh + off) = pack_h2(x0, x1);
                }
            }
        }
    }
}

// ==================== output projection ====================
__global__ void __launch_bounds__(256, 2) oproj_hmma(float* __restrict__ outp) {
    extern __shared__ char smraw[];
    int m0 = blockIdx.y * 128, n0 = blockIdx.x * 128;

    GemmOut o;
    gemm_hmma(g_ao, g_wh + (size_t)3 * (CC*CC), m0, n0, smraw, o);

    const int tid = threadIdx.x;
    const int wid = tid >> 5;
    const int lane = tid & 31;
    const int wm = (wid >> 2) * 64;
    const int wn = (wid & 3) * 32;

    int nbase = n0 + wn + (lane & 3) * 2;
    #pragma unroll
    for (int i = 0; i < 4; i++) {
        #pragma unroll
        for (int rr = 0; rr < 2; rr++) {
            int m = m0 + wm + i * 16 + (lane >> 2) + rr * 8;
            #pragma unroll
            for (int j = 0; j < 4; j++) {
                int n = nbase + j * 8;
                *(float2*)(outp + (size_t)m * CC + n) =
                    make_float2(o.acc[i][j][rr*2 + 0], o.acc[i][j][rr*2 + 1]);
            }
        }
    }
}

// ==================== HMMA flash attention (causal, no-max softmax, fp16, SW128) ====================
// Q tile 128 rows; warp = 16 rows x full 128-col S stripe.
// smem: Qh | Kh x2 | Vh x2, each 128 rows x 128B swizzled = 16KB. Total 80KB.
#define ATILE 16384
#define ATTN_SMEM (5*ATILE)   // 81920

__global__ void __launch_bounds__(256) attn_hmma() {
    extern __shared__ char smraw[];
    uint32_t sb = smem_u32(smraw);
    uint32_t sQh = sb;
    uint32_t sK0 = sb + ATILE,    sK1 = sb + 2*ATILE;
    uint32_t sV0 = sb + 3*ATILE,  sV1 = sb + 4*ATILE;

    const int tid = threadIdx.x;
    const int wid = tid >> 5;
    const int lane = tid & 31;
    const int bh = blockIdx.y;
    const int b = bh >> 4, h = bh & 15;

    const char* qhb = (const char*)(g_qh + (size_t)bh * (CT*CD));
    const char* khb = (const char*)(g_kh + (size_t)bh * (CT*CD));
    const char* vhb = (const char*)(g_vh + (size_t)bh * (CT*CD));

    // load mapping: 1024 chunks, 4 per thread, swizzled STS
    int rowc[4], colc[4];
    uint32_t smc[4];
    #pragma unroll
    for (int i = 0; i < 4; i++) {
        int c = tid + 256 * i;
        int r = c >> 3, j = c & 7;
        rowc[i] = r;
        colc[i] = j * 16;
        smc[i] = swz(r, j);
    }

    // Q frag addressing
    const int qrow = wid*16 + (lane & 15);
    const int qs7  = qrow & 7;
    const int qc0  = lane >> 4;
    const uint32_t qrb = (uint32_t)(qrow * 128);

    // K frag addressing (row within a 16-row group)
    const int klr = (lane & 7) + ((lane >> 4) & 1) * 8;
    const int kc0 = (lane >> 3) & 1;

    // V frag addressing
    const int vlr = (lane & 7) + ((lane >> 3) & 1) * 8;
    const int vc0 = (lane >> 4) & 1;

    #pragma unroll 1
    for (int pass = 0; pass < 2; pass++) {
        int qt = (pass == 0) ? blockIdx.x : 7 - blockIdx.x;

        #pragma unroll
        for (int i = 0; i < 4; i++) {
            long g = (long)(qt*128 + rowc[i]) * 128 + colc[i];
            cpasync16(sQh + smc[i], qhb + g);
        }
        CP_COMMIT();
        #pragma unroll
        for (int i = 0; i < 4; i++) {
            long g = (long)(rowc[i]) * 128 + colc[i];   // kt = 0
            cpasync16(sK0 + smc[i], khb + g);
            cpasync16(sV0 + smc[i], vhb + g);
        }
        CP_COMMIT();

        CP_WAIT1();        // Q group done
        __syncthreads();

        uint32_t qf[4][4];
        #pragma unroll
        for (int ks = 0; ks < 4; ks++) {
            uint32_t q_ad = sQh + qrb + (uint32_t)((((ks*2 + qc0) ^ qs7)) << 4);
            LDSM_X4(qf[ks][0], qf[ks][1], qf[ks][2], qf[ks][3], q_ad);
        }

        float o[8][4];
        #pragma unroll
        for (int j = 0; j < 8; j++)
            #pragma unroll
            for (int q = 0; q < 4; q++) o[j][q] = 0.f;
        float lsum0 = 0.f, lsum1 = 0.f;

        #pragma unroll 1
        for (int kt = 0; kt <= qt; kt++) {
            CP_WAIT0();
            __syncthreads();
            if (kt < qt) {
                uint32_t sKn = ((kt+1) & 1) ? sK1 : sK0;
                uint32_t sVn = ((kt+1) & 1) ? sV1 : sV0;
                #pragma unroll
                for (int i = 0; i < 4; i++) {
                    long g = (long)((kt+1)*128 + rowc[i]) * 128 + colc[i];
                    cpasync16(sKn + smc[i], khb + g);
                    cpasync16(sVn + smc[i], vhb + g);
                }
                CP_COMMIT();
            }
            uint32_t sKh = (kt & 1) ? sK1 : sK0;
            uint32_t sVh = (kt & 1) ? sV1 : sV0;

            // ---- S = Q K^T, warp stripe 16 x 128 ----
            float s[16][4];
            #pragma unroll
            for (int f = 0; f < 16; f++)
                #pragma unroll
                for (int q = 0; q < 4; q++) s[f][q] = 0.f;

            #pragma unroll
            for (int ks = 0; ks < 4; ks++) {
                #pragma unroll
                for (int g = 0; g < 8; g++) {
                    int krow = g*16 + klr;
                    uint32_t k_ad = sKh + (uint32_t)(krow * 128)
                                  + (uint32_t)((((ks*2 + kc0) ^ (krow & 7))) << 4);
                    uint32_t k4[4];
                    LDSM_X4(k4[0], k4[1], k4[2], k4[3], k_ad);
                    MMA_F16(s[2*g],   qf[ks], k4[0], k4[1]);
                    MMA_F16(s[2*g+1], qf[ks], k4[2], k4[3]);
                }
            }

            // ---- P = exp2(S) (+ causal mask on diag), pack fp16, row sums ----
            bool diag = (kt == qt);
            int lrow = wid*16 + (lane >> 2);
            uint32_t ph_[16][2];
            #pragma unroll
            for (int f = 0; f < 16; f++) {
                int lcol = 8*f + 2*(lane & 3);
                float p0 = ex2f(s[f][0]);
                float p1 = ex2f(s[f][1]);
                float p2 = ex2f(s[f][2]);
                float p3 = ex2f(s[f][3]);
                if (diag) {
                    if (lcol     > lrow)     p0 = 0.f;
                    if (lcol + 1 > lrow)     p1 = 0.f;
                    if (lcol     > lrow + 8) p2 = 0.f;
                    if (lcol + 1 > lrow + 8) p3 = 0.f;
                }
                lsum0 += p0 + p1;
                lsum1 += p2 + p3;
                ph_[f][0] = pack_h2(p0, p1);
                ph_[f][1] = pack_h2(p2, p3);
            }

            // ---- O += P V ----
            #pragma unroll
            for (int ks = 0; ks < 8; ks++) {
                uint32_t ah[4] = {ph_[2*ks][0], ph_[2*ks][1], ph_[2*ks+1][0], ph_[2*ks+1][1]};
                int vrow = ks*16 + vlr;
                uint32_t vrb = sVh + (uint32_t)(vrow * 128);
                int v7 = vrow & 7;
                #pragma unroll
                for (int g2 = 0; g2 < 4; g2++) {
                    uint32_t v_ad = vrb + (uint32_t)((((g2*2 + vc0) ^ v7)) << 4);
                    uint32_t v4[4];
                    LDSM_X4T(v4[0], v4[1], v4[2], v4[3], v_ad);
                    MMA_F16(o[2*g2],   ah, v4[0], v4[1]);
                    MMA_F16(o[2*g2+1], ah, v4[2], v4[3]);
                }
            }
        }

        lsum0 += __shfl_xor_sync(0xffffffffu, lsum0, 1);
        lsum0 += __shfl_xor_sync(0xffffffffu, lsum0, 2);
        lsum1 += __shfl_xor_sync(0xffffffffu, lsum1, 1);
        lsum1 += __shfl_xor_sync(0xffffffffu, lsum1, 2);
        float inv0 = 1.0f / lsum0;
        float inv1 = 1.0f / lsum1;

        int t0g = qt*128 + wid*16 + (lane >> 2);
        #pragma unroll
        for (int j = 0; j < 8; j++) {
            int d = 8*j + 2*(lane & 3);
            size_t off0 = ((size_t)(b*CT) + t0g) * CC + h*CD + d;
            size_t off1 = off0 + (size_t)8 * CC;
            *(uint32_t*)(g_ao + off0) = pack_h2(o[j][0]*inv0, o[j][1]*inv0);
            *(uint32_t*)(g_ao + off1) = pack_h2(o[j][2]*inv1, o[j][3]*inv1);
        }
        __syncthreads();
    }
}

// ==================== launch ====================
extern "C" void kernel_launch(void* const* d_in, const int* in_sizes, int n_in,
                              void* d_out, int out_size)
{
    const float* x  = (const float*)d_in[0];
    const float* Wq = (const float*)d_in[1];
    const float* Wk = (const float*)d_in[2];
    const float* Wv = (const float*)d_in[3];
    const float* Wo = (const float*)d_in[4];
    float* outp = (float*)d_out;

    cudaFuncSetAttribute(qkv_hmma, cudaFuncAttributeMaxDynamicSharedMemorySize, GEMM_SMEM);
    cudaFuncSetAttribute(oproj_hmma, cudaFuncAttributeMaxDynamicSharedMemorySize, GEMM_SMEM);
    cudaFuncSetAttribute(attn_hmma, cudaFuncAttributeMaxDynamicSharedMemorySize, ATTN_SMEM);

    prepass_kernel<<<1152, 256>>>(x, Wq, Wk, Wv, Wo);

    dim3 gqkv(CC/128, CM/128, 3);    // (8, 32, 3)
    qkv_hmma<<<gqkv, 256, GEMM_SMEM>>>();

    dim3 gattn(4, CB*CH);            // qtile pairs (qt, 7-qt) x 64 bh
    attn_hmma<<<gattn, 256, ATTN_SMEM>>>();

    dim3 gout(CC/128, CM/128);       // (8, 32)
    oproj_hmma<<<gout, 256, GEMM_SMEM>>>(outp);
}